// round 9
// baseline (speedup 1.0000x reference)
#include <cuda_runtime.h>
#include <cuda_bf16.h>
#include <stdint.h>
#include <math.h>

// ---------------- problem constants ----------------
#define BB 32
#define HH 56
#define WW 56
#define CC 192
#define WS 7
#define SHIFT 3
#define HEADS 6
#define HID 768
#define NN 49
#define NWIN 64
#define HD 32
#define TOK (BB*HH*WW)   // 100352

// weight scratch offsets (floats)
#define W_QKV 0
#define W_PROJ 110592
#define W_FC1 147456
#define W_FC2 294912
#define W_TOTAL 442368

// ---------------- scratch ----------------
__device__ float g_hwin[(size_t)TOK * CC];
__device__ float g_qkv [(size_t)TOK * 3 * CC];
__device__ float g_obuf[(size_t)TOK * CC];
__device__ float g_x1  [(size_t)TOK * CC];
__device__ float g_m1  [(size_t)TOK * HID];
__device__ float g_wr  [W_TOTAL];
__device__ float g_bm  [(size_t)HEADS * NWIN * NN * 50];   // bias+mask, col-padded to 50

__device__ __forceinline__ unsigned int f2tf(float f) {
    unsigned int u;
    asm("cvt.rna.tf32.f32 %0, %1;" : "=r"(u) : "f"(f));
    return u;
}
__device__ __forceinline__ float f2tf_f(float f) { return __uint_as_float(f2tf(f)); }

__device__ __forceinline__ void cp16(void* sp, const void* gp) {
    unsigned int sa = (unsigned int)__cvta_generic_to_shared(sp);
    asm volatile("cp.async.ca.shared.global [%0], [%1], 16;" :: "r"(sa), "l"(gp));
}

#define MMA(acc, A0, A1, A2, A3, B0, B1)                                    \
    asm("mma.sync.aligned.m16n8k8.row.col.f32.tf32.tf32.f32 "               \
        "{%0,%1,%2,%3}, {%4,%5,%6,%7}, {%8,%9}, {%0,%1,%2,%3};"             \
        : "+f"(acc[0]), "+f"(acc[1]), "+f"(acc[2]), "+f"(acc[3])            \
        : "r"(A0), "r"(A1), "r"(A2), "r"(A3), "r"(B0), "r"(B1))

// ---------------- weight pre-round (tf32 rna) ----------------
__global__ void round_w_kernel(const float* __restrict__ a, const float* __restrict__ b,
                               const float* __restrict__ c, const float* __restrict__ d,
                               float* __restrict__ o)
{
    int i = blockIdx.x * 256 + threadIdx.x;
    if (i >= W_TOTAL) return;
    float v;
    if (i < W_PROJ)       v = a[i - W_QKV];
    else if (i < W_FC1)   v = b[i - W_PROJ];
    else if (i < W_FC2)   v = c[i - W_FC1];
    else                  v = d[i - W_FC2];
    o[i] = f2tf_f(v);
}

// ---------------- bias+mask fold: bm[head][wi][i][j(pad 50)] ----------------
__global__ void bm_kernel(const float* __restrict__ bias_table,
                          const int*   __restrict__ rel_index,
                          const float* __restrict__ mask,
                          float* __restrict__ bm)
{
    int idx = blockIdx.x * 256 + threadIdx.x;
    if (idx >= HEADS * NWIN * NN * NN) return;
    int head = idx / (NWIN * NN * NN);
    int r    = idx % (NWIN * NN * NN);
    int wi   = r / (NN * NN);
    int ij   = r % (NN * NN);
    bm[((size_t)(head * NWIN + wi) * NN + ij / NN) * 50 + ij % NN] =
        bias_table[rel_index[ij] * HEADS + head] + mask[(size_t)wi * NN * NN + ij];
}

// ---------------- LayerNorm (1 warp/row); output tf32-rounded ----------------
template<bool WINDOW_MAP>
__global__ void ln_kernel(const float* __restrict__ x,
                          const float* __restrict__ w,
                          const float* __restrict__ b,
                          float* __restrict__ out)
{
    int row  = blockIdx.x * (blockDim.x >> 5) + (threadIdx.x >> 5);
    int lane = threadIdx.x & 31;
    if (row >= TOK) return;

    int src;
    if (WINDOW_MAP) {
        int widx = row / NN;
        int n    = row % NN;
        int bb   = widx / NWIN;
        int wi   = widx % NWIN;
        int wh   = wi / (WW / WS);
        int ww   = wi % (WW / WS);
        int hs   = wh * WS + n / WS;
        int ws   = ww * WS + n % WS;
        int h0   = (hs + SHIFT) % HH;
        int w0   = (ws + SHIFT) % WW;
        src = (bb * HH + h0) * WW + w0;
    } else {
        src = row;
    }

    const float* xr = x + (size_t)src * CC;
    float v[6];
    float s = 0.f;
#pragma unroll
    for (int i = 0; i < 6; i++) { v[i] = xr[lane + 32 * i]; s += v[i]; }
#pragma unroll
    for (int o = 16; o; o >>= 1) s += __shfl_xor_sync(0xffffffffu, s, o);
    float mu = s * (1.0f / CC);
    float vs = 0.f;
#pragma unroll
    for (int i = 0; i < 6; i++) { float d = v[i] - mu; vs += d * d; }
#pragma unroll
    for (int o = 16; o; o >>= 1) vs += __shfl_xor_sync(0xffffffffu, vs, o);
    float rstd = rsqrtf(vs * (1.0f / CC) + 1e-5f);

    float* orow = out + (size_t)row * CC;
#pragma unroll
    for (int i = 0; i < 6; i++) {
        int c = lane + 32 * i;
        orow[c] = f2tf_f((v[i] - mu) * rstd * w[c] + b[c]);
    }
}

// ---------------- TF32 tensor-core GEMM, cp.async double-buffered ----------------
#define ASZ (128*36)
#define BSZ (32*68)
#define GEMM_SMEM ((2*ASZ + 2*BSZ)*4)

template<int K, int EPI>
__global__ __launch_bounds__(128)
void gemm_tc2(const float* __restrict__ A, const float* __restrict__ Wt,
              const float* __restrict__ bias, const float* __restrict__ aux,
              float* __restrict__ Cc, int Nc)
{
    extern __shared__ float sm[];

    int tid  = threadIdx.x;
    int lane = tid & 31;
    int warp = tid >> 5;
    int g = lane >> 2;
    int q = lane & 3;
    int wm = (warp >> 1) * 64;
    int wn = (warp & 1) * 32;
    int m0 = blockIdx.y * 128;
    int n0 = blockIdx.x * 64;

    int a_m  = tid >> 3;
    int a_kc = (tid & 7) * 4;
    int b_k  = tid >> 4;
    int b_nc = (tid & 15) * 4;

    const float* Ab = A + (size_t)m0 * K + a_kc;
    const float* Bb = Wt + n0 + b_nc;

    float acc[4][4][4] = {};
    constexpr int KT = K / 32;

#define ISSUE(kt, s) do {                                                   \
        float* as_ = sm + (s) * ASZ;                                        \
        float* bs_ = sm + 2 * ASZ + (s) * BSZ;                              \
        _Pragma("unroll")                                                   \
        for (int j = 0; j < 8; j++) {                                       \
            int m_ = a_m + j * 16;                                          \
            cp16(&as_[m_ * 36 + a_kc], Ab + (size_t)m_ * K + (kt) * 32);    \
        }                                                                   \
        _Pragma("unroll")                                                   \
        for (int j = 0; j < 4; j++) {                                       \
            int k_ = b_k + j * 8;                                           \
            cp16(&bs_[k_ * 68 + b_nc], Bb + (size_t)((kt) * 32 + k_) * Nc); \
        }                                                                   \
        asm volatile("cp.async.commit_group;");                             \
    } while (0)

    ISSUE(0, 0);
    for (int kt = 0; kt < KT; kt++) {
        if (kt + 1 < KT) { ISSUE(kt + 1, (kt + 1) & 1); }
        else             { asm volatile("cp.async.commit_group;"); }
        asm volatile("cp.async.wait_group 1;");
        __syncthreads();

        const float* as = sm + (kt & 1) * ASZ;
        const float* bs = sm + 2 * ASZ + (kt & 1) * BSZ;
#pragma unroll
        for (int ks = 0; ks < 4; ks++) {
            int kk = ks * 8;
            unsigned int a[4][4], b[4][2];
#pragma unroll
            for (int mi = 0; mi < 4; mi++) {
                int mm = wm + mi * 16 + g;
                a[mi][0] = __float_as_uint(as[mm * 36 + kk + q]);
                a[mi][1] = __float_as_uint(as[(mm + 8) * 36 + kk + q]);
                a[mi][2] = __float_as_uint(as[mm * 36 + kk + q + 4]);
                a[mi][3] = __float_as_uint(as[(mm + 8) * 36 + kk + q + 4]);
            }
#pragma unroll
            for (int ni = 0; ni < 4; ni++) {
                int nn = wn + ni * 8 + g;
                b[ni][0] = __float_as_uint(bs[(kk + q) * 68 + nn]);
                b[ni][1] = __float_as_uint(bs[(kk + q + 4) * 68 + nn]);
            }
#pragma unroll
            for (int mi = 0; mi < 4; mi++)
#pragma unroll
                for (int ni = 0; ni < 4; ni++)
                    MMA(acc[mi][ni], a[mi][0], a[mi][1], a[mi][2], a[mi][3],
                        b[ni][0], b[ni][1]);
        }
        __syncthreads();
    }
#undef ISSUE

    // ---- epilogue ----
#pragma unroll
    for (int mi = 0; mi < 4; mi++) {
#pragma unroll
        for (int h = 0; h < 2; h++) {
            int row = m0 + wm + mi * 16 + g + h * 8;
            size_t base;
            if (EPI == 2) {
                int widx = row / NN;
                int n    = row % NN;
                int bimg = widx >> 6;
                int wi   = widx & 63;
                int hs = (wi >> 3) * WS + n / WS;
                int ws = (wi & 7) * WS + n % WS;
                int h2 = hs + SHIFT; if (h2 >= HH) h2 -= HH;
                int w2 = ws + SHIFT; if (w2 >= WW) w2 -= WW;
                base = (size_t)((bimg * HH + h2) * WW + w2) * CC;
            } else {
                base = (size_t)row * Nc;
            }
#pragma unroll
            for (int ni = 0; ni < 4; ni++) {
                int col = n0 + wn + ni * 8 + 2 * q;
                float c0 = acc[mi][ni][2 * h + 0] + bias[col];
                float c1 = acc[mi][ni][2 * h + 1] + bias[col + 1];
                if (EPI == 1) {
                    c0 = f2tf_f(0.5f * c0 * (1.0f + erff(c0 * 0.70710678118654752f)));
                    c1 = f2tf_f(0.5f * c1 * (1.0f + erff(c1 * 0.70710678118654752f)));
                }
                size_t idx = base + col;
                if (EPI == 2 || EPI == 3) {
                    float2 av = *(const float2*)(aux + idx);
                    c0 += av.x; c1 += av.y;
                }
                float2 o; o.x = c0; o.y = c1;
                *(float2*)(Cc + idx) = o;
            }
        }
    }
}

// ---------------- tensor-core attention: block = (window, head), 4 warps ----------------
__global__ __launch_bounds__(128)
void attn_tc(const float* __restrict__ qkv,
             const float* __restrict__ bm,
             float* __restrict__ obuf)
{
    int head = blockIdx.x % HEADS;
    int widx = blockIdx.x / HEADS;
    int wi   = widx & 63;

    __shared__ float Qs[64][40];   // row-major, stride 40 (mod 32 == 8)
    __shared__ float Ks[56][40];
    __shared__ float Vs[56][40];
    __shared__ float Ss[64][72];   // P matrix, stride 72 (mod 32 == 8)

    int tid  = threadIdx.x;
    int warp = tid >> 5;
    int lane = tid & 31;
    int g = lane >> 2;
    int q = lane & 3;
    const float scale = 0.17677669529663687f;

    // ---- load q,k,v (tf32-rounded) ----
    for (int idx = tid; idx < NN * HD; idx += 128) {
        int i = idx >> 5, d = idx & 31;
        size_t base = (size_t)(widx * NN + i) * (3 * CC) + head * HD + d;
        Qs[i][d] = f2tf_f(qkv[base] * scale);
        Ks[i][d] = f2tf_f(qkv[base + CC]);
        Vs[i][d] = f2tf_f(qkv[base + 2 * CC]);
    }
    // zero pad rows
    for (int idx = tid; idx < 15 * 32; idx += 128) {
        int i = idx >> 5, d = idx & 31;
        Qs[NN + i][d] = 0.f;
        if (i < 7) { Ks[NN + i][d] = 0.f; Vs[NN + i][d] = 0.f; }
    }
    __syncthreads();

    int mrow = warp * 16;

    // ---- S = Q @ K^T : 7 n-tiles x 4 k-steps ----
    float c[7][4] = {};
#pragma unroll
    for (int kk = 0; kk < 32; kk += 8) {
        unsigned int a0 = __float_as_uint(Qs[mrow + g][kk + q]);
        unsigned int a1 = __float_as_uint(Qs[mrow + g + 8][kk + q]);
        unsigned int a2 = __float_as_uint(Qs[mrow + g][kk + q + 4]);
        unsigned int a3 = __float_as_uint(Qs[mrow + g + 8][kk + q + 4]);
#pragma unroll
        for (int ni = 0; ni < 7; ni++) {
            unsigned int b0 = __float_as_uint(Ks[ni * 8 + g][kk + q]);
            unsigned int b1 = __float_as_uint(Ks[ni * 8 + g][kk + q + 4]);
            MMA(c[ni], a0, a1, a2, a3, b0, b1);
        }
    }

    // ---- bias+mask + softmax in registers (rows r0 = mrow+g, r1 = r0+8) ----
    int r0 = mrow + g, r1 = r0 + 8;
    const float* bmb = bm + (size_t)(head * NWIN + wi) * NN * 50;
#pragma unroll
    for (int ni = 0; ni < 7; ni++) {
        int col = ni * 8 + 2 * q;
        if (r0 < NN) {
            if (col + 1 < NN) {
                float2 bv = *(const float2*)(bmb + r0 * 50 + col);
                c[ni][0] += bv.x; c[ni][1] += bv.y;
            } else if (col < NN) {
                c[ni][0] += bmb[r0 * 50 + col]; c[ni][1] = -1e30f;
            } else { c[ni][0] = -1e30f; c[ni][1] = -1e30f; }
        }
        if (r1 < NN) {
            if (col + 1 < NN) {
                float2 bv = *(const float2*)(bmb + r1 * 50 + col);
                c[ni][2] += bv.x; c[ni][3] += bv.y;
            } else if (col < NN) {
                c[ni][2] += bmb[r1 * 50 + col]; c[ni][3] = -1e30f;
            } else { c[ni][2] = -1e30f; c[ni][3] = -1e30f; }
        }
    }
    float mx0 = -1e30f, mx1 = -1e30f;
#pragma unroll
    for (int ni = 0; ni < 7; ni++) {
        mx0 = fmaxf(mx0, fmaxf(c[ni][0], c[ni][1]));
        mx1 = fmaxf(mx1, fmaxf(c[ni][2], c[ni][3]));
    }
    mx0 = fmaxf(mx0, __shfl_xor_sync(0xffffffffu, mx0, 1));
    mx0 = fmaxf(mx0, __shfl_xor_sync(0xffffffffu, mx0, 2));
    mx1 = fmaxf(mx1, __shfl_xor_sync(0xffffffffu, mx1, 1));
    mx1 = fmaxf(mx1, __shfl_xor_sync(0xffffffffu, mx1, 2));
    float s0 = 0.f, s1 = 0.f;
#pragma unroll
    for (int ni = 0; ni < 7; ni++) {
        c[ni][0] = __expf(c[ni][0] - mx0);
        c[ni][1] = __expf(c[ni][1] - mx0);
        c[ni][2] = __expf(c[ni][2] - mx1);
        c[ni][3] = __expf(c[ni][3] - mx1);
        s0 += c[ni][0] + c[ni][1];
        s1 += c[ni][2] + c[ni][3];
    }
    s0 += __shfl_xor_sync(0xffffffffu, s0, 1);
    s0 += __shfl_xor_sync(0xffffffffu, s0, 2);
    s1 += __shfl_xor_sync(0xffffffffu, s1, 1);
    s1 += __shfl_xor_sync(0xffffffffu, s1, 2);
    float i0 = 1.0f / s0, i1 = 1.0f / s1;

    // ---- store P (tf32-rounded) ----
#pragma unroll
    for (int ni = 0; ni < 7; ni++) {
        int col = ni * 8 + 2 * q;
        float2 p0; p0.x = f2tf_f(c[ni][0] * i0); p0.y = f2tf_f(c[ni][1] * i0);
        float2 p1; p1.x = f2tf_f(c[ni][2] * i1); p1.y = f2tf_f(c[ni][3] * i1);
        *(float2*)&Ss[r0][col] = p0;
        *(float2*)&Ss[r1][col] = p1;
    }
    __syncwarp();

    // ---- O = P @ V : 4 n-tiles x 7 k-steps ----
    float o[4][4] = {};
#pragma unroll
    for (int ks = 0; ks < 7; ks++) {
        int kk = ks * 8;
        unsigned int a0 = __float_as_uint(Ss[mrow + g][kk + q]);
        unsigned int a1 = __float_as_uint(Ss[mrow + g + 8][kk + q]);
        unsigned int a2 = __float_as_uint(Ss[mrow + g][kk + q + 4]);
        unsigned int a3 = __float_as_uint(Ss[mrow + g + 8][kk + q + 4]);
#pragma unroll
        for (int ni = 0; ni < 4; ni++) {
            unsigned int b0 = __float_as_uint(Vs[kk + q][ni * 8 + g]);
            unsigned int b1 = __float_as_uint(Vs[kk + q + 4][ni * 8 + g]);
            MMA(o[ni], a0, a1, a2, a3, b0, b1);
        }
    }

    // ---- write O (tf32-rounded, A-operand of proj gemm) ----
#pragma unroll
    for (int ni = 0; ni < 4; ni++) {
        int col = head * HD + ni * 8 + 2 * q;
        if (r0 < NN) {
            float2 w; w.x = f2tf_f(o[ni][0]); w.y = f2tf_f(o[ni][1]);
            *(float2*)&obuf[(size_t)(widx * NN + r0) * CC + col] = w;
        }
        if (r1 < NN) {
            float2 w; w.x = f2tf_f(o[ni][2]); w.y = f2tf_f(o[ni][3]);
            *(float2*)&obuf[(size_t)(widx * NN + r1) * CC + col] = w;
        }
    }
}

// ---------------- launch ----------------
extern "C" void kernel_launch(void* const* d_in, const int* in_sizes, int n_in,
                              void* d_out, int out_size)
{
    const float* x          = (const float*)d_in[0];
    const float* norm1_w    = (const float*)d_in[1];
    const float* norm1_b    = (const float*)d_in[2];
    const float* qkv_w      = (const float*)d_in[3];
    const float* qkv_b      = (const float*)d_in[4];
    const float* bias_table = (const float*)d_in[5];
    const float* proj_w     = (const float*)d_in[6];
    const float* proj_b     = (const float*)d_in[7];
    const float* norm2_w    = (const float*)d_in[8];
    const float* norm2_b    = (const float*)d_in[9];
    const float* fc1_w      = (const float*)d_in[10];
    const float* fc1_b      = (const float*)d_in[11];
    const float* fc2_w      = (const float*)d_in[12];
    const float* fc2_b      = (const float*)d_in[13];
    const float* attn_mask  = (const float*)d_in[14];
    const int*   rel_index  = (const int*)  d_in[15];
    float* out = (float*)d_out;

    float *hwin, *qkv, *obuf, *x1, *m1, *wr, *bm;
    cudaGetSymbolAddress((void**)&hwin, g_hwin);
    cudaGetSymbolAddress((void**)&qkv,  g_qkv);
    cudaGetSymbolAddress((void**)&obuf, g_obuf);
    cudaGetSymbolAddress((void**)&x1,   g_x1);
    cudaGetSymbolAddress((void**)&m1,   g_m1);
    cudaGetSymbolAddress((void**)&wr,   g_wr);
    cudaGetSymbolAddress((void**)&bm,   g_bm);

    cudaFuncSetAttribute(gemm_tc2<192,0>, cudaFuncAttributeMaxDynamicSharedMemorySize, GEMM_SMEM);
    cudaFuncSetAttribute(gemm_tc2<192,1>, cudaFuncAttributeMaxDynamicSharedMemorySize, GEMM_SMEM);
    cudaFuncSetAttribute(gemm_tc2<192,2>, cudaFuncAttributeMaxDynamicSharedMemorySize, GEMM_SMEM);
    cudaFuncSetAttribute(gemm_tc2<768,3>, cudaFuncAttributeMaxDynamicSharedMemorySize, GEMM_SMEM);

    // 0. pre-round weights + fold bias/mask table
    round_w_kernel<<<(W_TOTAL + 255) / 256, 256>>>(qkv_w, proj_w, fc1_w, fc2_w, wr);
    bm_kernel<<<(HEADS * NWIN * NN * NN + 255) / 256, 256>>>(bias_table, rel_index, attn_mask, bm);

    // 1. LN1 + shift + window partition (rounded)
    ln_kernel<true><<<TOK / 8, 256>>>(x, norm1_w, norm1_b, hwin);

    // 2. QKV gemm
    gemm_tc2<192,0><<<dim3(9, TOK / 128), 128, GEMM_SMEM>>>(hwin, wr + W_QKV, qkv_b, nullptr, qkv, 576);

    // 3. tensor-core attention
    attn_tc<<<(TOK / NN) * HEADS, 128>>>(qkv, bm, obuf);

    // 4. proj gemm + window-reverse scatter + residual(x) -> x1
    gemm_tc2<192,2><<<dim3(3, TOK / 128), 128, GEMM_SMEM>>>(obuf, wr + W_PROJ, proj_b, x, x1, CC);

    // 5. LN2 (rounded)
    ln_kernel<false><<<TOK / 8, 256>>>(x1, norm2_w, norm2_b, hwin);

    // 6. fc1 + gelu (rounded)
    gemm_tc2<192,1><<<dim3(12, TOK / 128), 128, GEMM_SMEM>>>(hwin, wr + W_FC1, fc1_b, nullptr, m1, HID);

    // 7. fc2 + residual -> out
    gemm_tc2<768,3><<<dim3(3, TOK / 128), 128, GEMM_SMEM>>>(m1, wr + W_FC2, fc2_b, x1, out, CC);
}

// round 13
// speedup vs baseline: 1.8237x; 1.8237x over previous
#include <cuda_runtime.h>
#include <cuda_bf16.h>
#include <stdint.h>
#include <math.h>

// ---------------- problem constants ----------------
#define BB 32
#define HH 56
#define WW 56
#define CC 192
#define WS 7
#define SHIFT 3
#define HEADS 6
#define HID 768
#define NN 49
#define NWIN 64
#define HD 32
#define TOK (BB*HH*WW)   // 100352

// weight scratch offsets (elements)
#define W_QKV 0
#define W_PROJ 110592
#define W_FC1 147456
#define W_FC2 294912
#define W_TOTAL 442368

// ---------------- scratch ----------------
__device__ __nv_bfloat16 g_hwin[(size_t)TOK * CC];       // LN out (bf16 A-operand)
__device__ float         g_qkv [(size_t)TOK * 3 * CC];   // qkv (fp32, attn reads)
__device__ __nv_bfloat16 g_obuf[(size_t)TOK * CC];       // attn out (bf16 A-operand)
__device__ float         g_x1  [(size_t)TOK * CC];       // x + attn branch (fp32)
__device__ __nv_bfloat16 g_m1  [(size_t)TOK * HID];      // gelu out (bf16 A-operand)
__device__ __nv_bfloat16 g_wt  [W_TOTAL];                // weights, transposed [N][K] bf16

__device__ __forceinline__ void cp16(void* sp, const void* gp) {
    unsigned int sa = (unsigned int)__cvta_generic_to_shared(sp);
    asm volatile("cp.async.ca.shared.global [%0], [%1], 16;" :: "r"(sa), "l"(gp));
}

__device__ __forceinline__ __nv_bfloat162 pack_bf2(float lo, float hi) {
    return __floats2bfloat162_rn(lo, hi);
}

#define MMA_BF(acc, A0, A1, A2, A3, B0, B1)                                 \
    asm("mma.sync.aligned.m16n8k16.row.col.f32.bf16.bf16.f32 "              \
        "{%0,%1,%2,%3}, {%4,%5,%6,%7}, {%8,%9}, {%0,%1,%2,%3};"             \
        : "+f"(acc[0]), "+f"(acc[1]), "+f"(acc[2]), "+f"(acc[3])            \
        : "r"(A0), "r"(A1), "r"(A2), "r"(A3), "r"(B0), "r"(B1))

// ---------------- weight transpose + bf16: wt[n][k] = bf16(W[k][n]) ----------------
__global__ void round_wt_kernel(const float* __restrict__ a, const float* __restrict__ b,
                                const float* __restrict__ c, const float* __restrict__ d,
                                __nv_bfloat16* __restrict__ o)
{
    int i = blockIdx.x * 256 + threadIdx.x;
    if (i >= W_TOTAL) return;
    const float* src; int off, K_, N_;
    if (i < W_PROJ)      { src = a; off = W_QKV;  K_ = 192; N_ = 576; }
    else if (i < W_FC1)  { src = b; off = W_PROJ; K_ = 192; N_ = 192; }
    else if (i < W_FC2)  { src = c; off = W_FC1;  K_ = 192; N_ = 768; }
    else                 { src = d; off = W_FC2;  K_ = 768; N_ = 192; }
    int il = i - off;
    int n = il / K_, k = il % K_;
    o[i] = __float2bfloat16(src[(size_t)k * N_ + n]);
}

// ---------------- LayerNorm (1 warp/row) -> bf16, optional shift+window gather ----------------
template<bool WINDOW_MAP>
__global__ void ln_kernel(const float* __restrict__ x,
                          const float* __restrict__ w,
                          const float* __restrict__ b,
                          __nv_bfloat16* __restrict__ out)
{
    int row  = blockIdx.x * (blockDim.x >> 5) + (threadIdx.x >> 5);
    int lane = threadIdx.x & 31;
    if (row >= TOK) return;

    int src;
    if (WINDOW_MAP) {
        int widx = row / NN;
        int n    = row % NN;
        int bb   = widx / NWIN;
        int wi   = widx % NWIN;
        int wh   = wi / (WW / WS);
        int ww   = wi % (WW / WS);
        int hs   = wh * WS + n / WS;
        int ws   = ww * WS + n % WS;
        int h0   = (hs + SHIFT) % HH;
        int w0   = (ws + SHIFT) % WW;
        src = (bb * HH + h0) * WW + w0;
    } else {
        src = row;
    }

    const float* xr = x + (size_t)src * CC;
    float2 v[3];
    float s = 0.f;
#pragma unroll
    for (int i = 0; i < 3; i++) {
        v[i] = *(const float2*)(xr + 2 * lane + 64 * i);
        s += v[i].x + v[i].y;
    }
#pragma unroll
    for (int o = 16; o; o >>= 1) s += __shfl_xor_sync(0xffffffffu, s, o);
    float mu = s * (1.0f / CC);
    float vs = 0.f;
#pragma unroll
    for (int i = 0; i < 3; i++) {
        float d0 = v[i].x - mu, d1 = v[i].y - mu;
        vs += d0 * d0 + d1 * d1;
    }
#pragma unroll
    for (int o = 16; o; o >>= 1) vs += __shfl_xor_sync(0xffffffffu, vs, o);
    float rstd = rsqrtf(vs * (1.0f / CC) + 1e-5f);

    __nv_bfloat16* orow = out + (size_t)row * CC;
#pragma unroll
    for (int i = 0; i < 3; i++) {
        int c = 2 * lane + 64 * i;
        float y0 = (v[i].x - mu) * rstd * w[c]     + b[c];
        float y1 = (v[i].y - mu) * rstd * w[c + 1] + b[c + 1];
        *(__nv_bfloat162*)(orow + c) = pack_bf2(y0, y1);
    }
}

// ---------------- bf16 tensor-core GEMM, cp.async double-buffered ----------------
// BM=128, BN=64, BK=32. 128 threads = 4 warps (2m x 2n), warp tile 64x32.
// A [M][K] bf16 row-major; Wt [N][K] bf16 (pre-transposed).
// EPI: 0 = bias -> float; 1 = bias+gelu -> bf16;
//      2 = bias + residual(aux, gathered) + window-reverse scatter -> float;
//      3 = bias + residual(aux) -> float
template<int K, int EPI>
__global__ __launch_bounds__(128)
void gemm_bf(const __nv_bfloat16* __restrict__ A, const __nv_bfloat16* __restrict__ Wt,
             const float* __restrict__ bias, const float* __restrict__ aux,
             float* __restrict__ Cf, __nv_bfloat16* __restrict__ Cb, int Nc)
{
    __shared__ __nv_bfloat16 As[2][128 * 40];   // row stride 40 bf16 = 20 words -> conflict-free
    __shared__ __nv_bfloat16 Bs[2][64 * 40];

    int tid  = threadIdx.x;
    int lane = tid & 31;
    int warp = tid >> 5;
    int g = lane >> 2;
    int q = lane & 3;
    int wm = (warp >> 1) * 64;
    int wn = (warp & 1) * 32;
    int m0 = blockIdx.y * 128;
    int n0 = blockIdx.x * 64;

    int a_m  = tid >> 2;          // + 32j, j<4
    int a_kc = (tid & 3) * 8;     // bf16 units
    int b_n  = tid >> 2;          // + 32j, j<2
    int b_kc = (tid & 3) * 8;

    float acc[4][4][4] = {};
    constexpr int KT = K / 32;

#define ISSUE(kt, st) do {                                                          \
        __nv_bfloat16* as_ = As[st];                                                \
        __nv_bfloat16* bs_ = Bs[st];                                                \
        _Pragma("unroll")                                                           \
        for (int j = 0; j < 4; j++) {                                               \
            int m_ = a_m + 32 * j;                                                  \
            cp16(as_ + m_ * 40 + a_kc, A + (size_t)(m0 + m_) * K + (kt) * 32 + a_kc); \
        }                                                                           \
        _Pragma("unroll")                                                           \
        for (int j = 0; j < 2; j++) {                                               \
            int n_ = b_n + 32 * j;                                                  \
            cp16(bs_ + n_ * 40 + b_kc, Wt + (size_t)(n0 + n_) * K + (kt) * 32 + b_kc); \
        }                                                                           \
        asm volatile("cp.async.commit_group;");                                     \
    } while (0)

    ISSUE(0, 0);
    for (int kt = 0; kt < KT; kt++) {
        if (kt + 1 < KT) { ISSUE(kt + 1, (kt + 1) & 1); }
        else             { asm volatile("cp.async.commit_group;"); }
        asm volatile("cp.async.wait_group 1;");
        __syncthreads();

        const unsigned int* as32 = (const unsigned int*)As[kt & 1];
        const unsigned int* bs32 = (const unsigned int*)Bs[kt & 1];
#pragma unroll
        for (int ks = 0; ks < 2; ks++) {
            int kw = ks * 8;   // word offset of this k16 half
            unsigned int a[4][4], b[4][2];
#pragma unroll
            for (int mi = 0; mi < 4; mi++) {
                int mm = wm + mi * 16 + g;
                a[mi][0] = as32[mm * 20 + kw + q];
                a[mi][1] = as32[(mm + 8) * 20 + kw + q];
                a[mi][2] = as32[mm * 20 + kw + q + 4];
                a[mi][3] = as32[(mm + 8) * 20 + kw + q + 4];
            }
#pragma unroll
            for (int ni = 0; ni < 4; ni++) {
                int nn = wn + ni * 8 + g;
                b[ni][0] = bs32[nn * 20 + kw + q];
                b[ni][1] = bs32[nn * 20 + kw + q + 4];
            }
#pragma unroll
            for (int mi = 0; mi < 4; mi++)
#pragma unroll
                for (int ni = 0; ni < 4; ni++)
                    MMA_BF(acc[mi][ni], a[mi][0], a[mi][1], a[mi][2], a[mi][3],
                           b[ni][0], b[ni][1]);
        }
        __syncthreads();
    }
#undef ISSUE

    // ---- epilogue ----
#pragma unroll
    for (int mi = 0; mi < 4; mi++) {
#pragma unroll
        for (int h = 0; h < 2; h++) {
            int row = m0 + wm + mi * 16 + g + h * 8;
            size_t base;
            if (EPI == 2) {
                int widx = row / NN;
                int n    = row % NN;
                int bimg = widx >> 6;
                int wi   = widx & 63;
                int hs = (wi >> 3) * WS + n / WS;
                int ws = (wi & 7) * WS + n % WS;
                int h2 = hs + SHIFT; if (h2 >= HH) h2 -= HH;
                int w2 = ws + SHIFT; if (w2 >= WW) w2 -= WW;
                base = (size_t)((bimg * HH + h2) * WW + w2) * CC;
            } else {
                base = (size_t)row * Nc;
            }
#pragma unroll
            for (int ni = 0; ni < 4; ni++) {
                int col = n0 + wn + ni * 8 + 2 * q;
                float c0 = acc[mi][ni][2 * h + 0] + bias[col];
                float c1 = acc[mi][ni][2 * h + 1] + bias[col + 1];
                size_t idx = base + col;
                if (EPI == 1) {
                    c0 = 0.5f * c0 * (1.0f + erff(c0 * 0.70710678118654752f));
                    c1 = 0.5f * c1 * (1.0f + erff(c1 * 0.70710678118654752f));
                    *(__nv_bfloat162*)(Cb + idx) = pack_bf2(c0, c1);
                } else {
                    if (EPI == 2 || EPI == 3) {
                        float2 av = *(const float2*)(aux + idx);
                        c0 += av.x; c1 += av.y;
                    }
                    float2 o; o.x = c0; o.y = c1;
                    *(float2*)(Cf + idx) = o;
                }
            }
        }
    }
}

// ---------------- attention (SIMT, fp32 in / bf16 out): block per (window, head) ----------------
__global__ __launch_bounds__(128)
void attn_kernel(const float* __restrict__ qkv,
                 const float* __restrict__ bias_table,
                 const int*   __restrict__ rel_index,
                 const float* __restrict__ mask,
                 __nv_bfloat16* __restrict__ obuf)
{
    int blk  = blockIdx.x;
    int head = blk % HEADS;
    int widx = blk / HEADS;
    int wi   = widx % NWIN;

    __shared__ float q[NN][HD + 1], k[NN][HD + 1], v[NN][HD + 1];
    __shared__ float s[NN][NN + 1];

    int tid = threadIdx.x;
    const float scale = 0.17677669529663687f;

    for (int idx = tid; idx < NN * HD; idx += 128) {
        int i = idx >> 5;
        int d = idx & 31;
        size_t base = (size_t)(widx * NN + i) * (3 * CC);
        q[i][d] = qkv[base + head * HD + d] * scale;
        k[i][d] = qkv[base + CC + head * HD + d];
        v[i][d] = qkv[base + 2 * CC + head * HD + d];
    }
    __syncthreads();

    const float* mrow = mask + (size_t)wi * NN * NN;
    for (int u = tid; u < NN * 7; u += 128) {
        int i  = u / 7;
        int jg = u % 7;
        float a[7] = {};
#pragma unroll
        for (int d = 0; d < HD; d++) {
            float qd = q[i][d];
#pragma unroll
            for (int jj = 0; jj < 7; jj++)
                a[jj] = fmaf(qd, k[jg * 7 + jj][d], a[jj]);
        }
#pragma unroll
        for (int jj = 0; jj < 7; jj++) {
            int j = jg * 7 + jj;
            a[jj] += bias_table[rel_index[i * NN + j] * HEADS + head] + mrow[i * NN + j];
            s[i][j] = a[jj];
        }
    }
    __syncthreads();

    int warp = tid >> 5, lane = tid & 31;
    for (int i = warp; i < NN; i += 4) {
        float x1 = s[i][lane];
        float x2 = (lane + 32 < NN) ? s[i][lane + 32] : -1e30f;
        float m = fmaxf(x1, x2);
#pragma unroll
        for (int o = 16; o; o >>= 1) m = fmaxf(m, __shfl_xor_sync(0xffffffffu, m, o));
        float e1 = __expf(x1 - m);
        float e2 = (lane + 32 < NN) ? __expf(x2 - m) : 0.f;
        float sum = e1 + e2;
#pragma unroll
        for (int o = 16; o; o >>= 1) sum += __shfl_xor_sync(0xffffffffu, sum, o);
        float inv = 1.0f / sum;
        s[i][lane] = e1 * inv;
        if (lane + 32 < NN) s[i][lane + 32] = e2 * inv;
    }
    __syncthreads();

    for (int r = warp; r < NN; r += 4) {
        float a0 = 0.f, a1 = 0.f;
#pragma unroll
        for (int j = 0; j < 48; j += 2) {
            a0 = fmaf(s[r][j],     v[j][lane],     a0);
            a1 = fmaf(s[r][j + 1], v[j + 1][lane], a1);
        }
        a0 = fmaf(s[r][48], v[48][lane], a0);
        obuf[(size_t)(widx * NN + r) * CC + head * HD + lane] = __float2bfloat16(a0 + a1);
    }
}

// ---------------- launch ----------------
extern "C" void kernel_launch(void* const* d_in, const int* in_sizes, int n_in,
                              void* d_out, int out_size)
{
    const float* x          = (const float*)d_in[0];
    const float* norm1_w    = (const float*)d_in[1];
    const float* norm1_b    = (const float*)d_in[2];
    const float* qkv_w      = (const float*)d_in[3];
    const float* qkv_b      = (const float*)d_in[4];
    const float* bias_table = (const float*)d_in[5];
    const float* proj_w     = (const float*)d_in[6];
    const float* proj_b     = (const float*)d_in[7];
    const float* norm2_w    = (const float*)d_in[8];
    const float* norm2_b    = (const float*)d_in[9];
    const float* fc1_w      = (const float*)d_in[10];
    const float* fc1_b      = (const float*)d_in[11];
    const float* fc2_w      = (const float*)d_in[12];
    const float* fc2_b      = (const float*)d_in[13];
    const float* attn_mask  = (const float*)d_in[14];
    const int*   rel_index  = (const int*)  d_in[15];
    float* out = (float*)d_out;

    __nv_bfloat16 *hwin, *obuf, *m1, *wt;
    float *qkv, *x1;
    cudaGetSymbolAddress((void**)&hwin, g_hwin);
    cudaGetSymbolAddress((void**)&qkv,  g_qkv);
    cudaGetSymbolAddress((void**)&obuf, g_obuf);
    cudaGetSymbolAddress((void**)&x1,   g_x1);
    cudaGetSymbolAddress((void**)&m1,   g_m1);
    cudaGetSymbolAddress((void**)&wt,   g_wt);

    // 0. weights -> bf16 transposed [N][K]
    round_wt_kernel<<<(W_TOTAL + 255) / 256, 256>>>(qkv_w, proj_w, fc1_w, fc2_w, wt);

    // 1. LN1 + shift + window partition -> bf16
    ln_kernel<true><<<TOK / 8, 256>>>(x, norm1_w, norm1_b, hwin);

    // 2. QKV gemm -> fp32
    gemm_bf<192,0><<<dim3(9, TOK / 128), 128>>>(hwin, wt + W_QKV, qkv_b, nullptr, qkv, nullptr, 576);

    // 3. attention -> bf16
    attn_kernel<<<(TOK / NN) * HEADS, 128>>>(qkv, bias_table, rel_index, attn_mask, obuf);

    // 4. proj gemm + window-reverse scatter + residual(x) -> x1 (fp32)
    gemm_bf<192,2><<<dim3(3, TOK / 128), 128>>>(obuf, wt + W_PROJ, proj_b, x, x1, nullptr, CC);

    // 5. LN2 -> bf16
    ln_kernel<false><<<TOK / 8, 256>>>(x1, norm2_w, norm2_b, hwin);

    // 6. fc1 + gelu -> bf16
    gemm_bf<192,1><<<dim3(12, TOK / 128), 128>>>(hwin, wt + W_FC1, fc1_b, nullptr, nullptr, m1, HID);

    // 7. fc2 + residual(x1) -> out (fp32)
    gemm_bf<768,3><<<dim3(3, TOK / 128), 128>>>(m1, wt + W_FC2, fc2_b, x1, out, nullptr, CC);
}